// round 16
// baseline (speedup 1.0000x reference)
#include <cuda_runtime.h>
#include <cstdint>

// Problem constants
#define B_   4
#define S_   2048
#define H_   16
#define DK_  64
#define D_   1024
#define M_   (B_*S_)   // 8192

// Scratch (allocation-free rule: __device__ globals)
__device__ float g_Wq[(size_t)D_*D_]; // tf32-pre-rounded weights, TRANSPOSED [N][K]
__device__ float g_Wk[(size_t)D_*D_];
__device__ float g_Wv[(size_t)D_*D_];
__device__ float g_Wo[(size_t)D_*D_];
__device__ float g_Q[B_*H_*S_*DK_];   // [B,H,S,DK], tf32-rounded, scaled by 0.125*log2e
__device__ float g_K[B_*H_*S_*DK_];   // [B,H,S,DK]
__device__ float g_V[B_*H_*S_*DK_];   // [B,H,DK,S]  (TRANSPOSED for ldmatrix)
__device__ float g_AO[(size_t)M_*D_]; // attention output, tf32-rounded, [B*S, D]

// ---------------------------------------------------------------------------
// helpers
// ---------------------------------------------------------------------------
__device__ __forceinline__ uint32_t f2tf(float f) {
    uint32_t u;
    asm("cvt.rna.tf32.f32 %0, %1;" : "=r"(u) : "f"(f));
    return u;
}

__device__ __forceinline__ float ex2(float x) {
    float y;
    asm("ex2.approx.f32 %0, %1;" : "=f"(y) : "f"(x));
    return y;
}

__device__ __forceinline__ void mma8(float* d, const uint32_t* a, const uint32_t* b) {
    asm volatile(
        "mma.sync.aligned.m16n8k8.row.col.f32.tf32.tf32.f32 "
        "{%0,%1,%2,%3}, {%4,%5,%6,%7}, {%8,%9}, {%0,%1,%2,%3};"
        : "+f"(d[0]), "+f"(d[1]), "+f"(d[2]), "+f"(d[3])
        : "r"(a[0]), "r"(a[1]), "r"(a[2]), "r"(a[3]),
          "r"(b[0]), "r"(b[1]));
}

__device__ __forceinline__ void ldsm4(uint32_t* r, uint32_t saddr) {
    asm volatile(
        "ldmatrix.sync.aligned.m8n8.x4.shared.b16 {%0,%1,%2,%3}, [%4];"
        : "=r"(r[0]), "=r"(r[1]), "=r"(r[2]), "=r"(r[3]) : "r"(saddr));
}

__device__ __forceinline__ void cp16(float* smem, const float* gmem) {
    uint32_t s = (uint32_t)__cvta_generic_to_shared(smem);
    asm volatile("cp.async.cg.shared.global [%0], [%1], 16;\n" :: "r"(s), "l"(gmem));
}
#define CP_COMMIT() asm volatile("cp.async.commit_group;\n" ::: "memory")
#define CP_WAIT0()  asm volatile("cp.async.wait_group 0;\n" ::: "memory")
#define CP_WAIT1()  asm volatile("cp.async.wait_group 1;\n" ::: "memory")

// ---------------------------------------------------------------------------
// Pre-round + TRANSPOSE W: src [K][N] -> dst [N][K]
// ---------------------------------------------------------------------------
__global__ void prep_w_kernel(const float* __restrict__ wq,
                              const float* __restrict__ wk,
                              const float* __restrict__ wv,
                              const float* __restrict__ wo)
{
    const float* src = (blockIdx.z == 0) ? wq : (blockIdx.z == 1) ? wk :
                       (blockIdx.z == 2) ? wv : wo;
    float* dst = (blockIdx.z == 0) ? g_Wq : (blockIdx.z == 1) ? g_Wk :
                 (blockIdx.z == 2) ? g_Wv : g_Wo;
    __shared__ float ts[32][33];
    const int k0 = blockIdx.x * 32;
    const int n0 = blockIdx.y * 32;
    const int tx = threadIdx.x, ty = threadIdx.y;   // 32 x 8
#pragma unroll
    for (int j = 0; j < 4; j++)
        ts[ty + 8 * j][tx] = src[(size_t)(k0 + ty + 8 * j) * D_ + n0 + tx];
    __syncthreads();
#pragma unroll
    for (int j = 0; j < 4; j++)
        dst[(size_t)(n0 + ty + 8 * j) * D_ + k0 + tx] =
            __uint_as_float(f2tf(ts[tx][ty + 8 * j]));
}

// ---------------------------------------------------------------------------
// 3-stage pipelined TF32 GEMM (unchanged from R14).
// ---------------------------------------------------------------------------
#define GEMM_ASTR 36
#define GEMM_BSTR 36
#define GEMM_TILE (128*GEMM_ASTR + 128*GEMM_BSTR)
#define GEMM_SMEM ((3 * GEMM_TILE) * 4)             // 110592 B

template<bool SCATTER, bool CVTA>
__device__ __forceinline__ void gemm_body(const float* __restrict__ X,
                                          const float* __restrict__ Wt,
                                          const float* __restrict__ bias,
                                          float* __restrict__ out,
                                          float oscale, bool vt)
{
    constexpr int BM = 128, BN = 128, BK = 32;
    constexpr int ASTR = GEMM_ASTR, BSTR = GEMM_BSTR;

    extern __shared__ float sm[];
    const uint32_t sm_u32 = (uint32_t)__cvta_generic_to_shared(sm);

    const int tid  = threadIdx.x;
    const int m0   = blockIdx.y * BM;
    const int n0   = blockIdx.x * BN;
    const int wid  = tid >> 5;
    const int lane = tid & 31;
    const int g    = lane >> 2;
    const int t    = lane & 3;
    const int wm   = (wid >> 1) * 64;
    const int wn   = (wid & 1) * 64;

    const int rowa = (lane & 7) + ((lane >> 3) & 1) * 8;
    const int cola = (lane >> 4) * 4;
    const int rowb = (lane & 7) + (lane >> 4) * 8;
    const int colb = ((lane >> 3) & 1) * 4;

    float acc[4][8][4];
#pragma unroll
    for (int i = 0; i < 4; i++)
#pragma unroll
        for (int j = 0; j < 8; j++)
#pragma unroll
            for (int e = 0; e < 4; e++) acc[i][j][e] = 0.f;

    auto issue = [&](int k0, int buf) {
        float* As = sm + buf * GEMM_TILE;
        float* Bs = As + BM * ASTR;
#pragma unroll
        for (int i = 0; i < 8; i++) {
            int idx = tid + i * 128;
            int r = idx >> 3, c4 = idx & 7;
            cp16(&As[r * ASTR + c4 * 4], &X[(size_t)(m0 + r) * D_ + k0 + c4 * 4]);
        }
#pragma unroll
        for (int i = 0; i < 8; i++) {
            int idx = tid + i * 128;
            int r = idx >> 3, c4 = idx & 7;
            cp16(&Bs[r * BSTR + c4 * 4], &Wt[(size_t)(n0 + r) * D_ + k0 + c4 * 4]);
        }
    };

    constexpr int NT = D_ / BK;   // 32
    issue(0, 0); CP_COMMIT();
    issue(BK, 1); CP_COMMIT();

    int buf = 0;
    for (int it = 0; it < NT; it++) {
        if (it < NT - 1) { CP_WAIT1(); } else { CP_WAIT0(); }
        __syncthreads();
        if (it + 2 < NT) {
            int nb = buf + 2; if (nb >= 3) nb -= 3;
            issue((it + 2) * BK, nb);
            CP_COMMIT();
        }
        const uint32_t as_u32 = sm_u32 + buf * GEMM_TILE * 4;
        const uint32_t bs_u32 = as_u32 + BM * ASTR * 4;

#pragma unroll
        for (int kk = 0; kk < 4; kk++) {
            const int kb = kk * 8;
            uint32_t a4[4][4], b4[4][4];
#pragma unroll
            for (int mf = 0; mf < 4; mf++) {
                ldsm4(a4[mf], as_u32 + (((wm + mf * 16 + rowa) * ASTR + kb + cola) << 2));
                if (CVTA) {
#pragma unroll
                    for (int e = 0; e < 4; e++)
                        a4[mf][e] = f2tf(__uint_as_float(a4[mf][e]));
                }
            }
#pragma unroll
            for (int nfp = 0; nfp < 4; nfp++)
                ldsm4(b4[nfp], bs_u32 + (((wn + nfp * 16 + rowb) * BSTR + kb + colb) << 2));
#pragma unroll
            for (int mf = 0; mf < 4; mf++)
#pragma unroll
                for (int nfp = 0; nfp < 4; nfp++) {
                    mma8(acc[mf][2 * nfp],     a4[mf], &b4[nfp][0]);
                    mma8(acc[mf][2 * nfp + 1], a4[mf], &b4[nfp][2]);
                }
        }
        buf++; if (buf >= 3) buf = 0;
    }

#pragma unroll
    for (int mf = 0; mf < 4; mf++) {
#pragma unroll
        for (int nf = 0; nf < 8; nf++) {
            int r0 = m0 + wm + mf * 16 + g;
            int c0 = n0 + wn + nf * 8 + 2 * t;
#pragma unroll
            for (int rr = 0; rr < 2; rr++) {
                int r = r0 + rr * 8;
#pragma unroll
                for (int cc = 0; cc < 2; cc++) {
                    int c = c0 + cc;
                    float v = acc[mf][nf][rr * 2 + cc] + bias[c];
                    if (SCATTER) {
                        v = __uint_as_float(f2tf(v * oscale));
                        int bb = r >> 11;
                        int s  = r & (S_ - 1);
                        int h  = c >> 6;
                        int dk = c & (DK_ - 1);
                        if (vt)
                            out[(((size_t)(bb * H_ + h)) * DK_ + dk) * S_ + s] = v;
                        else
                            out[(((size_t)(bb * H_ + h)) * S_ + s) * DK_ + dk] = v;
                    } else {
                        out[(size_t)r * D_ + c] = v;
                    }
                }
            }
        }
    }
}

__global__ __launch_bounds__(128, 2)
void qkv_gemm_kernel(const float* __restrict__ xq,
                     const float* __restrict__ xk,
                     const float* __restrict__ xv,
                     const float* __restrict__ bq,
                     const float* __restrict__ bk,
                     const float* __restrict__ bv)
{
    const int z = blockIdx.z;
    const float* X = (z == 0) ? xq : (z == 1) ? xk : xv;   // RAW fp32 inputs
    const float* W = (z == 0) ? g_Wq : (z == 1) ? g_Wk : g_Wv;
    const float* bb = (z == 0) ? bq : (z == 1) ? bk : bv;
    float* out = (z == 0) ? g_Q : (z == 1) ? g_K : g_V;
    const float sc = (z == 0) ? 0.125f * 1.4426950408889634f : 1.0f;
    gemm_body<true, true>(X, W, bb, out, sc, z == 2);
}

__global__ __launch_bounds__(128, 2)
void out_gemm_kernel(const float* __restrict__ bo, float* __restrict__ out)
{
    gemm_body<false, false>(g_AO, g_Wo, bo, out, 1.0f, false);
}

// ---------------------------------------------------------------------------
// Causal FlashAttention, SHIFT-FREE softmax, half-tile deferred PV.
// KT=64, 2-stage K/V ring. RACE FIX vs R15: a second __syncthreads separates
// the pending-PV reads of the old V buffer from the cp.async that overwrites
// it (2-stage ring has no spare buffer, so the barrier is mandatory).
// Barriers: 2 per 64-col tile (same rate as KT=32); loader calls, CP_WAITs
// and mask checks are halved. smem 106496 B -> 2 CTAs/SM.
// ---------------------------------------------------------------------------
#define KSTR 68
#define VSTR 68
#define PSTR 36
#define KT_  64
#define QROWS 128
#define ATTN_KB (KT_*KSTR)               // floats per K stage
#define ATTN_VB (64*VSTR)                // floats per V stage
#define ATTN_HPB (32*PSTR)               // floats per P half-buffer per warp
#define ATTN_SMEM ((2*ATTN_KB + 2*ATTN_VB + 2*4*ATTN_HPB) * 4)  // 106496 B

__global__ __launch_bounds__(128, 2)
void attn_kernel()
{
    extern __shared__ float sm[];
    const uint32_t sm_u32 = (uint32_t)__cvta_generic_to_shared(sm);

    const int tid  = threadIdx.x;
    const int wid  = tid >> 5;
    const int lane = tid & 31;
    const int g    = lane >> 2;
    const int t    = lane & 3;
    const int bh   = blockIdx.y;
    const int qt   = gridDim.x - 1 - blockIdx.x;   // heavy tiles first

    const int rowa = (lane & 7) + ((lane >> 3) & 1) * 8;
    const int cola = (lane >> 4) * 4;
    const int rowb = (lane & 7) + (lane >> 4) * 8;
    const int colb = ((lane >> 3) & 1) * 4;

    const float* Qp = g_Q + (size_t)bh * S_ * DK_ + (size_t)qt * QROWS * DK_;
    const float* Kp = g_K + (size_t)bh * S_ * DK_;
    const float* Vp = g_V + (size_t)bh * S_ * DK_;   // [DK][S]
    float* Pwarp = sm + 2 * ATTN_KB + 2 * ATTN_VB + wid * 2 * ATTN_HPB;
    const uint32_t pw_u32 = sm_u32 + (2 * ATTN_KB + 2 * ATTN_VB + wid * 2 * ATTN_HPB) * 4;

    // loader: K tile 64x64 (1024 f4), V^T tile 64x64 (1024 f4)
    auto issue = [&](int jt, int buf) {
        const float* Kt = Kp + (size_t)jt * KT_ * DK_;
        float* Ks = sm + buf * ATTN_KB;
        float* Vs = sm + 2 * ATTN_KB + buf * ATTN_VB;
        const int j0 = jt * KT_;
#pragma unroll
        for (int i = 0; i < 8; i++) {
            int idx = tid + i * 128;
            int r = idx >> 4, c4 = idx & 15;
            cp16(&Ks[r * KSTR + c4 * 4], &Kt[r * DK_ + c4 * 4]);
        }
#pragma unroll
        for (int i = 0; i < 8; i++) {
            int idx = tid + i * 128;
            int r = idx >> 4, c4 = idx & 15;
            cp16(&Vs[r * VSTR + c4 * 4], &Vp[(size_t)r * S_ + j0 + c4 * 4]);
        }
    };

    const int jtmax = 2 * qt + 1;
    issue(0, 0); CP_COMMIT();

    const int row_min = qt * QROWS + wid * 32;
    uint32_t qf[2][8][4];
#pragma unroll
    for (int mf = 0; mf < 2; mf++) {
        const int r = wid * 32 + mf * 16 + g;
#pragma unroll
        for (int kk = 0; kk < 8; kk++) {
            const int kb = kk * 8;
            qf[mf][kk][0] = __float_as_uint(Qp[r * DK_ + kb + t]);
            qf[mf][kk][1] = __float_as_uint(Qp[(r + 8) * DK_ + kb + t]);
            qf[mf][kk][2] = __float_as_uint(Qp[r * DK_ + kb + t + 4]);
            qf[mf][kk][3] = __float_as_uint(Qp[(r + 8) * DK_ + kb + t + 4]);
        }
    }

    float l_i[2][2] = {{0.f, 0.f}, {0.f, 0.f}};   // per-LANE partial sums
    float accO[2][8][4];
#pragma unroll
    for (int mf = 0; mf < 2; mf++)
#pragma unroll
        for (int nf = 0; nf < 8; nf++)
#pragma unroll
            for (int e = 0; e < 4; e++) accO[mf][nf][e] = 0.f;

    float sc_[2][4][4];

    // QK of one 32-col half (h = 0/1) of K tile in kbuf
    auto qk_half = [&](int jt, int kbuf, int h) {
        const uint32_t ks_u32 = sm_u32 + kbuf * ATTN_KB * 4 + (h * 32) * KSTR * 4;
#pragma unroll
        for (int mf = 0; mf < 2; mf++)
#pragma unroll
            for (int nf = 0; nf < 4; nf++)
#pragma unroll
                for (int e = 0; e < 4; e++) sc_[mf][nf][e] = 0.f;
#pragma unroll
        for (int kk = 0; kk < 8; kk++) {
            const int kb = kk * 8;
            uint32_t kf[2][4];
            ldsm4(kf[0], ks_u32 + (((rowb) * KSTR + kb + colb) << 2));
            ldsm4(kf[1], ks_u32 + (((16 + rowb) * KSTR + kb + colb) << 2));
#pragma unroll
            for (int mf = 0; mf < 2; mf++) {
                mma8(sc_[mf][0], qf[mf][kk], &kf[0][0]);
                mma8(sc_[mf][1], qf[mf][kk], &kf[0][2]);
                mma8(sc_[mf][2], qf[mf][kk], &kf[1][0]);
                mma8(sc_[mf][3], qf[mf][kk], &kf[1][2]);
            }
        }
        const int c0 = jt * KT_ + h * 32;
        if (c0 + 31 > row_min) {
#pragma unroll
            for (int mf = 0; mf < 2; mf++)
#pragma unroll
                for (int nf = 0; nf < 4; nf++)
#pragma unroll
                    for (int e = 0; e < 4; e++) {
                        int rloc = row_min + mf * 16 + g + (e >> 1) * 8;
                        int cloc = c0 + nf * 8 + 2 * t + (e & 1);
                        if (cloc > rloc) sc_[mf][nf][e] = -1e30f;
                    }
        }
    };

    // PV: P half-buffer ph against V half vh of tile in vbuf
    auto pv = [&](int vbuf, int vh, int ph) {
        const uint32_t vs_u32 = sm_u32 + (2 * ATTN_KB + vbuf * ATTN_VB) * 4 + (vh * 32) * 4;
        const uint32_t pb = pw_u32 + ph * ATTN_HPB * 4;
#pragma unroll
        for (int kk = 0; kk < 4; kk++) {
            const int kb = kk * 8;
            uint32_t a4[2][4];
            ldsm4(a4[0], pb + (((rowa) * PSTR + kb + cola) << 2));
            ldsm4(a4[1], pb + (((16 + rowa) * PSTR + kb + cola) << 2));
            uint32_t v4[4][4];
#pragma unroll
            for (int nfp = 0; nfp < 4; nfp++)
                ldsm4(v4[nfp], vs_u32 + (((nfp * 16 + rowb) * VSTR + kb + colb) << 2));
#pragma unroll
            for (int nfp = 0; nfp < 4; nfp++) {
                mma8(accO[0][2 * nfp],     a4[0], &v4[nfp][0]);
                mma8(accO[0][2 * nfp + 1], a4[0], &v4[nfp][2]);
                mma8(accO[1][2 * nfp],     a4[1], &v4[nfp][0]);
                mma8(accO[1][2 * nfp + 1], a4[1], &v4[nfp][2]);
            }
        }
    };

    // shift-free softmax: p = ex2(s), lane-partial l, store into P half ph
    auto softmax_store = [&](int ph) {
        float* Pw = Pwarp + ph * ATTN_HPB;
#pragma unroll
        for (int mf = 0; mf < 2; mf++) {
#pragma unroll
            for (int nf = 0; nf < 4; nf++) {
                float p0 = ex2(sc_[mf][nf][0]);
                float p1 = ex2(sc_[mf][nf][1]);
                float p2 = ex2(sc_[mf][nf][2]);
                float p3 = ex2(sc_[mf][nf][3]);
                l_i[mf][0] += p0 + p1;
                l_i[mf][1] += p2 + p3;
                int c = nf * 8 + 2 * t;
                int rbase = mf * 16 + g;
                float2 q0 = { __uint_as_float(f2tf(p0)), __uint_as_float(f2tf(p1)) };
                float2 q1 = { __uint_as_float(f2tf(p2)), __uint_as_float(f2tf(p3)) };
                *(float2*)&Pw[rbase * PSTR + c]       = q0;
                *(float2*)&Pw[(rbase + 8) * PSTR + c] = q1;
            }
        }
        __syncwarp();
    };

    // ---- peeled jt = 0 ----
    CP_WAIT0();
    __syncthreads();
    issue(1, 1); CP_COMMIT();            // buffer 1 untouched: safe, no barrier needed
    qk_half(0, 0, 0);
    softmax_store(0);
    pv(0, 0, 0);
    qk_half(0, 0, 1);
    softmax_store(1);                    // pending: tile 0 half 1

    // ---- main loop ----
    for (int jt = 1; jt <= jtmax; jt++) {
        const int buf = jt & 1;
        CP_WAIT0();                      // tile jt data arrived
        __syncthreads();                 // all warps done K reads of tile jt-1
        pv(buf ^ 1, 1, 1);               // pending PV: prev tile h1 (old V buffer)
        __syncthreads();                 // RACE FIX: all warps done reading old V
        if (jt + 1 <= jtmax) {
            issue(jt + 1, buf ^ 1);      // now safe to overwrite prev buffers
            CP_COMMIT();
        }
        qk_half(jt, buf, 0);
        softmax_store(0);
        pv(buf, 0, 0);                   // current h0 PV overlaps h1's QK chain
        qk_half(jt, buf, 1);
        softmax_store(1);                // pending for next iteration
    }
    // final pending PV
    pv(jtmax & 1, 1, 1);

    // epilogue: quad-reduce lane-partial l, normalize, write [B,S,H*DK]
#pragma unroll
    for (int mf = 0; mf < 2; mf++)
#pragma unroll
        for (int off = 1; off <= 2; off <<= 1) {
            l_i[mf][0] += __shfl_xor_sync(0xffffffffu, l_i[mf][0], off);
            l_i[mf][1] += __shfl_xor_sync(0xffffffffu, l_i[mf][1], off);
        }

    const int b = bh / H_;
    const int h = bh % H_;
#pragma unroll
    for (int mf = 0; mf < 2; mf++) {
        const float inv0 = 1.f / l_i[mf][0];
        const float inv1 = 1.f / l_i[mf][1];
        const int s0 = qt * QROWS + wid * 32 + mf * 16 + g;
#pragma unroll
        for (int nf = 0; nf < 8; nf++) {
            int c = h * DK_ + nf * 8 + 2 * t;
            size_t r0 = ((size_t)(b * S_ + s0)) * D_;
            size_t r1 = ((size_t)(b * S_ + s0 + 8)) * D_;
            g_AO[r0 + c]     = __uint_as_float(f2tf(accO[mf][nf][0] * inv0));
            g_AO[r0 + c + 1] = __uint_as_float(f2tf(accO[mf][nf][1] * inv0));
            g_AO[r1 + c]     = __uint_as_float(f2tf(accO[mf][nf][2] * inv1));
            g_AO[r1 + c + 1] = __uint_as_float(f2tf(accO[mf][nf][3] * inv1));
        }
    }
}

// ---------------------------------------------------------------------------
extern "C" void kernel_launch(void* const* d_in, const int* in_sizes, int n_in,
                              void* d_out, int out_size)
{
    (void)in_sizes; (void)n_in; (void)out_size;
    const float* query = (const float*)d_in[0];
    const float* value = (const float*)d_in[1];
    const float* key   = (const float*)d_in[2];
    const float* Wq = (const float*)d_in[3];
    const float* bq = (const float*)d_in[4];
    const float* Wk = (const float*)d_in[5];
    const float* bk = (const float*)d_in[6];
    const float* Wv = (const float*)d_in[7];
    const float* bv = (const float*)d_in[8];
    const float* Wo = (const float*)d_in[9];
    const float* bo = (const float*)d_in[10];
    float* out = (float*)d_out;

    cudaFuncSetAttribute(attn_kernel, cudaFuncAttributeMaxDynamicSharedMemorySize, ATTN_SMEM);
    cudaFuncSetAttribute(qkv_gemm_kernel, cudaFuncAttributeMaxDynamicSharedMemorySize, GEMM_SMEM);
    cudaFuncSetAttribute(out_gemm_kernel, cudaFuncAttributeMaxDynamicSharedMemorySize, GEMM_SMEM);

    prep_w_kernel<<<dim3(D_ / 32, D_ / 32, 4), dim3(32, 8)>>>(Wq, Wk, Wv, Wo);
    qkv_gemm_kernel<<<dim3(D_ / 128, M_ / 128, 3), 128, GEMM_SMEM>>>(
        query, key, value, bq, bk, bv);
    attn_kernel<<<dim3(S_ / QROWS, B_ * H_), 128, ATTN_SMEM>>>();
    out_gemm_kernel<<<dim3(D_ / 128, M_ / 128), 128, GEMM_SMEM>>>(bo, out);
}

// round 17
// speedup vs baseline: 1.0213x; 1.0213x over previous
#include <cuda_runtime.h>
#include <cstdint>

// Problem constants
#define B_   4
#define S_   2048
#define H_   16
#define DK_  64
#define D_   1024
#define M_   (B_*S_)   // 8192

// Scratch (allocation-free rule: __device__ globals)
__device__ float g_Wq[(size_t)D_*D_]; // tf32-pre-rounded weights, TRANSPOSED [N][K]
__device__ float g_Wk[(size_t)D_*D_];
__device__ float g_Wv[(size_t)D_*D_];
__device__ float g_Wo[(size_t)D_*D_];
__device__ float g_Q[B_*H_*S_*DK_];   // [B,H,S,DK], tf32-rounded, scaled by 0.125*log2e
__device__ float g_K[B_*H_*S_*DK_];   // [B,H,S,DK]
__device__ float g_V[B_*H_*S_*DK_];   // [B,H,DK,S]  (TRANSPOSED for ldmatrix)
__device__ float g_AO[(size_t)M_*D_]; // attention output, tf32-rounded, [B*S, D]

// ---------------------------------------------------------------------------
// helpers
// ---------------------------------------------------------------------------
__device__ __forceinline__ uint32_t f2tf(float f) {
    uint32_t u;
    asm("cvt.rna.tf32.f32 %0, %1;" : "=r"(u) : "f"(f));
    return u;
}

__device__ __forceinline__ float ex2(float x) {
    float y;
    asm("ex2.approx.f32 %0, %1;" : "=f"(y) : "f"(x));
    return y;
}

__device__ __forceinline__ void mma8(float* d, const uint32_t* a, const uint32_t* b) {
    asm volatile(
        "mma.sync.aligned.m16n8k8.row.col.f32.tf32.tf32.f32 "
        "{%0,%1,%2,%3}, {%4,%5,%6,%7}, {%8,%9}, {%0,%1,%2,%3};"
        : "+f"(d[0]), "+f"(d[1]), "+f"(d[2]), "+f"(d[3])
        : "r"(a[0]), "r"(a[1]), "r"(a[2]), "r"(a[3]),
          "r"(b[0]), "r"(b[1]));
}

__device__ __forceinline__ void ldsm4(uint32_t* r, uint32_t saddr) {
    asm volatile(
        "ldmatrix.sync.aligned.m8n8.x4.shared.b16 {%0,%1,%2,%3}, [%4];"
        : "=r"(r[0]), "=r"(r[1]), "=r"(r[2]), "=r"(r[3]) : "r"(saddr));
}

__device__ __forceinline__ void cp16(float* smem, const float* gmem) {
    uint32_t s = (uint32_t)__cvta_generic_to_shared(smem);
    asm volatile("cp.async.cg.shared.global [%0], [%1], 16;\n" :: "r"(s), "l"(gmem));
}
#define CP_COMMIT() asm volatile("cp.async.commit_group;\n" ::: "memory")
#define CP_WAIT0()  asm volatile("cp.async.wait_group 0;\n" ::: "memory")
#define CP_WAIT1()  asm volatile("cp.async.wait_group 1;\n" ::: "memory")

// ---------------------------------------------------------------------------
// Pre-round + TRANSPOSE W: src [K][N] -> dst [N][K]
// ---------------------------------------------------------------------------
__global__ void prep_w_kernel(const float* __restrict__ wq,
                              const float* __restrict__ wk,
                              const float* __restrict__ wv,
                              const float* __restrict__ wo)
{
    const float* src = (blockIdx.z == 0) ? wq : (blockIdx.z == 1) ? wk :
                       (blockIdx.z == 2) ? wv : wo;
    float* dst = (blockIdx.z == 0) ? g_Wq : (blockIdx.z == 1) ? g_Wk :
                 (blockIdx.z == 2) ? g_Wv : g_Wo;
    __shared__ float ts[32][33];
    const int k0 = blockIdx.x * 32;
    const int n0 = blockIdx.y * 32;
    const int tx = threadIdx.x, ty = threadIdx.y;   // 32 x 8
#pragma unroll
    for (int j = 0; j < 4; j++)
        ts[ty + 8 * j][tx] = src[(size_t)(k0 + ty + 8 * j) * D_ + n0 + tx];
    __syncthreads();
#pragma unroll
    for (int j = 0; j < 4; j++)
        dst[(size_t)(n0 + ty + 8 * j) * D_ + k0 + tx] =
            __uint_as_float(f2tf(ts[tx][ty + 8 * j]));
}

// ---------------------------------------------------------------------------
// 3-stage pipelined TF32 GEMM. BM=128, BN=128, BK=32.
// 256 threads = 8 warps, each 32x64 (4x2 warp grid): halves per-thread regs
// -> 2 CTAs/SM of 256 thr = 16 warps/SM (was 8) to hide LDSM/MMA latency.
// W stored TRANSPOSED [N][K]. CVTA: tf32-round A fragments after ldmatrix.
// ---------------------------------------------------------------------------
#define GEMM_ASTR 36
#define GEMM_BSTR 36
#define GEMM_TILE (128*GEMM_ASTR + 128*GEMM_BSTR)
#define GEMM_SMEM ((3 * GEMM_TILE) * 4)             // 110592 B

template<bool SCATTER, bool CVTA>
__device__ __forceinline__ void gemm_body(const float* __restrict__ X,
                                          const float* __restrict__ Wt,
                                          const float* __restrict__ bias,
                                          float* __restrict__ out,
                                          float oscale, bool vt)
{
    constexpr int BM = 128, BN = 128, BK = 32;
    constexpr int ASTR = GEMM_ASTR, BSTR = GEMM_BSTR;

    extern __shared__ float sm[];
    const uint32_t sm_u32 = (uint32_t)__cvta_generic_to_shared(sm);

    const int tid  = threadIdx.x;
    const int m0   = blockIdx.y * BM;
    const int n0   = blockIdx.x * BN;
    const int wid  = tid >> 5;
    const int lane = tid & 31;
    const int g    = lane >> 2;
    const int t    = lane & 3;
    const int wm   = (wid >> 1) * 32;   // 0/32/64/96
    const int wn   = (wid & 1) * 64;    // 0/64

    const int rowa = (lane & 7) + ((lane >> 3) & 1) * 8;
    const int cola = (lane >> 4) * 4;
    const int rowb = (lane & 7) + (lane >> 4) * 8;
    const int colb = ((lane >> 3) & 1) * 4;

    float acc[2][8][4];
#pragma unroll
    for (int i = 0; i < 2; i++)
#pragma unroll
        for (int j = 0; j < 8; j++)
#pragma unroll
            for (int e = 0; e < 4; e++) acc[i][j][e] = 0.f;

    // loaders: A 128x32 = 1024 f4, B 128x32 = 1024 f4; 256 threads x 4 each
    auto issue = [&](int k0, int buf) {
        float* As = sm + buf * GEMM_TILE;
        float* Bs = As + BM * ASTR;
#pragma unroll
        for (int i = 0; i < 4; i++) {
            int idx = tid + i * 256;
            int r = idx >> 3, c4 = idx & 7;
            cp16(&As[r * ASTR + c4 * 4], &X[(size_t)(m0 + r) * D_ + k0 + c4 * 4]);
        }
#pragma unroll
        for (int i = 0; i < 4; i++) {
            int idx = tid + i * 256;
            int r = idx >> 3, c4 = idx & 7;
            cp16(&Bs[r * BSTR + c4 * 4], &Wt[(size_t)(n0 + r) * D_ + k0 + c4 * 4]);
        }
    };

    constexpr int NT = D_ / BK;   // 32
    issue(0, 0); CP_COMMIT();
    issue(BK, 1); CP_COMMIT();

    int buf = 0;
    for (int it = 0; it < NT; it++) {
        if (it < NT - 1) { CP_WAIT1(); } else { CP_WAIT0(); }
        __syncthreads();
        if (it + 2 < NT) {
            int nb = buf + 2; if (nb >= 3) nb -= 3;
            issue((it + 2) * BK, nb);
            CP_COMMIT();
        }
        const uint32_t as_u32 = sm_u32 + buf * GEMM_TILE * 4;
        const uint32_t bs_u32 = as_u32 + BM * ASTR * 4;

#pragma unroll
        for (int kk = 0; kk < 4; kk++) {
            const int kb = kk * 8;
            uint32_t a4[2][4], b4[4][4];
#pragma unroll
            for (int mf = 0; mf < 2; mf++) {
                ldsm4(a4[mf], as_u32 + (((wm + mf * 16 + rowa) * ASTR + kb + cola) << 2));
                if (CVTA) {
#pragma unroll
                    for (int e = 0; e < 4; e++)
                        a4[mf][e] = f2tf(__uint_as_float(a4[mf][e]));
                }
            }
#pragma unroll
            for (int nfp = 0; nfp < 4; nfp++)
                ldsm4(b4[nfp], bs_u32 + (((wn + nfp * 16 + rowb) * BSTR + kb + colb) << 2));
#pragma unroll
            for (int mf = 0; mf < 2; mf++)
#pragma unroll
                for (int nfp = 0; nfp < 4; nfp++) {
                    mma8(acc[mf][2 * nfp],     a4[mf], &b4[nfp][0]);
                    mma8(acc[mf][2 * nfp + 1], a4[mf], &b4[nfp][2]);
                }
        }
        buf++; if (buf >= 3) buf = 0;
    }

#pragma unroll
    for (int mf = 0; mf < 2; mf++) {
#pragma unroll
        for (int nf = 0; nf < 8; nf++) {
            int r0 = m0 + wm + mf * 16 + g;
            int c0 = n0 + wn + nf * 8 + 2 * t;
#pragma unroll
            for (int rr = 0; rr < 2; rr++) {
                int r = r0 + rr * 8;
#pragma unroll
                for (int cc = 0; cc < 2; cc++) {
                    int c = c0 + cc;
                    float v = acc[mf][nf][rr * 2 + cc] + bias[c];
                    if (SCATTER) {
                        v = __uint_as_float(f2tf(v * oscale));
                        int bb = r >> 11;
                        int s  = r & (S_ - 1);
                        int h  = c >> 6;
                        int dk = c & (DK_ - 1);
                        if (vt)
                            out[(((size_t)(bb * H_ + h)) * DK_ + dk) * S_ + s] = v;
                        else
                            out[(((size_t)(bb * H_ + h)) * S_ + s) * DK_ + dk] = v;
                    } else {
                        out[(size_t)r * D_ + c] = v;
                    }
                }
            }
        }
    }
}

__global__ __launch_bounds__(256, 2)
void qkv_gemm_kernel(const float* __restrict__ xq,
                     const float* __restrict__ xk,
                     const float* __restrict__ xv,
                     const float* __restrict__ bq,
                     const float* __restrict__ bk,
                     const float* __restrict__ bv)
{
    const int z = blockIdx.z;
    const float* X = (z == 0) ? xq : (z == 1) ? xk : xv;   // RAW fp32 inputs
    const float* W = (z == 0) ? g_Wq : (z == 1) ? g_Wk : g_Wv;
    const float* bb = (z == 0) ? bq : (z == 1) ? bk : bv;
    float* out = (z == 0) ? g_Q : (z == 1) ? g_K : g_V;
    const float sc = (z == 0) ? 0.125f * 1.4426950408889634f : 1.0f;
    gemm_body<true, true>(X, W, bb, out, sc, z == 2);
}

__global__ __launch_bounds__(256, 2)
void out_gemm_kernel(const float* __restrict__ bo, float* __restrict__ out)
{
    gemm_body<false, false>(g_AO, g_Wo, bo, out, 1.0f, false);
}

// ---------------------------------------------------------------------------
// Causal FlashAttention (R14 configuration — measured best at 251us).
// SHIFT-FREE softmax, deferred PV, lane-partial l.
// CTA: 128 Q-rows, 4 warps x 32 rows. KT=32. 3-stage K/V ring, double P.
// 2 CTAs/SM.
// ---------------------------------------------------------------------------
#define KSTR 68
#define VSTR 36
#define PSTR 36
#define KT_  32
#define QROWS 128
#define ATTN_KB (KT_*KSTR)
#define ATTN_VB (64*VSTR)
#define ATTN_PB (32*PSTR)
#define ATTN_SMEM ((3*ATTN_KB + 3*ATTN_VB + 2*4*ATTN_PB) * 4)  // 90624 B

__global__ __launch_bounds__(128, 2)
void attn_kernel()
{
    extern __shared__ float sm[];
    const uint32_t sm_u32 = (uint32_t)__cvta_generic_to_shared(sm);

    const int tid  = threadIdx.x;
    const int wid  = tid >> 5;
    const int lane = tid & 31;
    const int g    = lane >> 2;
    const int t    = lane & 3;
    const int bh   = blockIdx.y;
    const int qt   = gridDim.x - 1 - blockIdx.x;   // heavy tiles first

    const int rowa = (lane & 7) + ((lane >> 3) & 1) * 8;
    const int cola = (lane >> 4) * 4;
    const int rowb = (lane & 7) + (lane >> 4) * 8;
    const int colb = ((lane >> 3) & 1) * 4;

    const float* Qp = g_Q + (size_t)bh * S_ * DK_ + (size_t)qt * QROWS * DK_;
    const float* Kp = g_K + (size_t)bh * S_ * DK_;
    const float* Vp = g_V + (size_t)bh * S_ * DK_;   // [DK][S]
    float* Pwarp = sm + 3 * ATTN_KB + 3 * ATTN_VB + wid * 2 * ATTN_PB;
    const uint32_t pw_u32 = sm_u32 + (3 * ATTN_KB + 3 * ATTN_VB + wid * 2 * ATTN_PB) * 4;

    auto issue = [&](int jt, int buf) {
        const float* Kt = Kp + (size_t)jt * KT_ * DK_;
        float* Ks = sm + buf * ATTN_KB;
        float* Vs = sm + 3 * ATTN_KB + buf * ATTN_VB;
        const int j0 = jt * KT_;
#pragma unroll
        for (int i = 0; i < 4; i++) {
            int idx = tid + i * 128;
            int r = idx >> 4, c4 = idx & 15;
            cp16(&Ks[r * KSTR + c4 * 4], &Kt[r * DK_ + c4 * 4]);
        }
#pragma unroll
        for (int i = 0; i < 4; i++) {
            int idx = tid + i * 128;
            int r = idx >> 3, c4 = idx & 7;
            cp16(&Vs[r * VSTR + c4 * 4], &Vp[(size_t)r * S_ + j0 + c4 * 4]);
        }
    };

    const int jtmax = 4 * qt + 3;
    issue(0, 0); CP_COMMIT();

    const int row_min = qt * QROWS + wid * 32;
    uint32_t qf[2][8][4];
#pragma unroll
    for (int mf = 0; mf < 2; mf++) {
        const int r = wid * 32 + mf * 16 + g;
#pragma unroll
        for (int kk = 0; kk < 8; kk++) {
            const int kb = kk * 8;
            qf[mf][kk][0] = __float_as_uint(Qp[r * DK_ + kb + t]);
            qf[mf][kk][1] = __float_as_uint(Qp[(r + 8) * DK_ + kb + t]);
            qf[mf][kk][2] = __float_as_uint(Qp[r * DK_ + kb + t + 4]);
            qf[mf][kk][3] = __float_as_uint(Qp[(r + 8) * DK_ + kb + t + 4]);
        }
    }

    float l_i[2][2] = {{0.f, 0.f}, {0.f, 0.f}};   // per-LANE partial sums
    float accO[2][8][4];
#pragma unroll
    for (int mf = 0; mf < 2; mf++)
#pragma unroll
        for (int nf = 0; nf < 8; nf++)
#pragma unroll
            for (int e = 0; e < 4; e++) accO[mf][nf][e] = 0.f;

    float sc_[2][4][4];

    auto qk_mask = [&](int jt, int kbuf) {
        const uint32_t ks_u32 = sm_u32 + kbuf * ATTN_KB * 4;
#pragma unroll
        for (int mf = 0; mf < 2; mf++)
#pragma unroll
            for (int nf = 0; nf < 4; nf++)
#pragma unroll
                for (int e = 0; e < 4; e++) sc_[mf][nf][e] = 0.f;
#pragma unroll
        for (int kk = 0; kk < 8; kk++) {
            const int kb = kk * 8;
            uint32_t kf[2][4];
            ldsm4(kf[0], ks_u32 + (((rowb) * KSTR + kb + colb) << 2));
            ldsm4(kf[1], ks_u32 + (((16 + rowb) * KSTR + kb + colb) << 2));
#pragma unroll
            for (int mf = 0; mf < 2; mf++) {
                mma8(sc_[mf][0], qf[mf][kk], &kf[0][0]);
                mma8(sc_[mf][1], qf[mf][kk], &kf[0][2]);
                mma8(sc_[mf][2], qf[mf][kk], &kf[1][0]);
                mma8(sc_[mf][3], qf[mf][kk], &kf[1][2]);
            }
        }
        if (jt * KT_ + (KT_ - 1) > row_min) {
#pragma unroll
            for (int mf = 0; mf < 2; mf++)
#pragma unroll
                for (int nf = 0; nf < 4; nf++)
#pragma unroll
                    for (int e = 0; e < 4; e++) {
                        int rloc = row_min + mf * 16 + g + (e >> 1) * 8;
                        int cloc = jt * KT_ + nf * 8 + 2 * t + (e & 1);
                        if (cloc > rloc) sc_[mf][nf][e] = -1e30f;
                    }
        }
    };

    auto pv = [&](int vbuf, int pidx) {
        const uint32_t vs_u32 = sm_u32 + (3 * ATTN_KB + vbuf * ATTN_VB) * 4;
        const uint32_t pb = pw_u32 + pidx * ATTN_PB * 4;
#pragma unroll
        for (int kk = 0; kk < 4; kk++) {
            const int kb = kk * 8;
            uint32_t a4[2][4];
            ldsm4(a4[0], pb + (((rowa) * PSTR + kb + cola) << 2));
            ldsm4(a4[1], pb + (((16 + rowa) * PSTR + kb + cola) << 2));
            uint32_t v4[4][4];
#pragma unroll
            for (int nfp = 0; nfp < 4; nfp++)
                ldsm4(v4[nfp], vs_u32 + (((nfp * 16 + rowb) * VSTR + kb + colb) << 2));
#pragma unroll
            for (int nfp = 0; nfp < 4; nfp++) {
                mma8(accO[0][2 * nfp],     a4[0], &v4[nfp][0]);
                mma8(accO[0][2 * nfp + 1], a4[0], &v4[nfp][2]);
                mma8(accO[1][2 * nfp],     a4[1], &v4[nfp][0]);
                mma8(accO[1][2 * nfp + 1], a4[1], &v4[nfp][2]);
            }
        }
    };

    // shift-free softmax: p = ex2(s), lane-partial l, no max/rescale chain
    auto softmax_store = [&](int pidx) {
        float* Pw = Pwarp + pidx * ATTN_PB;
#pragma unroll
        for (int mf = 0; mf < 2; mf++) {
#pragma unroll
            for (int nf = 0; nf < 4; nf++) {
                float p0 = ex2(sc_[mf][nf][0]);
                float p1 = ex2(sc_[mf][nf][1]);
                float p2 = ex2(sc_[mf][nf][2]);
                float p3 = ex2(sc_[mf][nf][3]);
                l_i[mf][0] += p0 + p1;
                l_i[mf][1] += p2 + p3;
                int c = nf * 8 + 2 * t;
                int rbase = mf * 16 + g;
                float2 q0 = { __uint_as_float(f2tf(p0)), __uint_as_float(f2tf(p1)) };
                float2 q1 = { __uint_as_float(f2tf(p2)), __uint_as_float(f2tf(p3)) };
                *(float2*)&Pw[rbase * PSTR + c]       = q0;
                *(float2*)&Pw[(rbase + 8) * PSTR + c] = q1;
            }
        }
        __syncwarp();
    };

    // peeled jt = 0
    CP_WAIT0();
    __syncthreads();
    if (jtmax >= 1) { issue(1, 1); CP_COMMIT(); }
    qk_mask(0, 0);
    softmax_store(0);

    for (int jt = 1; jt <= jtmax; jt++) {
        int kbuf = jt % 3;
        CP_WAIT0();
        __syncthreads();
        if (jt + 1 <= jtmax) {
            int nb = kbuf + 1; if (nb >= 3) nb -= 3;
            issue(jt + 1, nb);
            CP_COMMIT();
        }
        qk_mask(jt, kbuf);
        pv(kbuf == 0 ? 2 : kbuf - 1, (jt - 1) & 1);
        softmax_store(jt & 1);
    }
    pv(jtmax % 3, jtmax & 1);

    // epilogue: quad-reduce lane-partial l, normalize, write [B,S,H*DK]
#pragma unroll
    for (int mf = 0; mf < 2; mf++)
#pragma unroll
        for (int off = 1; off <= 2; off <<= 1) {
            l_i[mf][0] += __shfl_xor_sync(0xffffffffu, l_i[mf][0], off);
            l_i[mf][1] += __shfl_xor_sync(0xffffffffu, l_i[mf][1], off);
        }

    const int b = bh / H_;
    const int h = bh % H_;
#pragma unroll
    for (int mf = 0; mf < 2; mf++) {
        const float inv0 = 1.f / l_i[mf][0];
        const float inv1 = 1.f / l_i[mf][1];
        const int s0 = qt * QROWS + wid * 32 + mf * 16 + g;
#pragma unroll
        for (int nf = 0; nf < 8; nf++) {
            int c = h * DK_ + nf * 8 + 2 * t;
            size_t r0 = ((size_t)(b * S_ + s0)) * D_;
            size_t r1 = ((size_t)(b * S_ + s0 + 8)) * D_;
            g_AO[r0 + c]     = __uint_as_float(f2tf(accO[mf][nf][0] * inv0));
            g_AO[r0 + c + 1] = __uint_as_float(f2tf(accO[mf][nf][1] * inv0));
            g_AO[r1 + c]     = __uint_as_float(f2tf(accO[mf][nf][2] * inv1));
            g_AO[r1 + c + 1] = __uint_as_float(f2tf(accO[mf][nf][3] * inv1));
        }
    }
}

// ---------------------------------------------------------------------------
extern "C" void kernel_launch(void* const* d_in, const int* in_sizes, int n_in,
                              void* d_out, int out_size)
{
    (void)in_sizes; (void)n_in; (void)out_size;
    const float* query = (const float*)d_in[0];
    const float* value = (const float*)d_in[1];
    const float* key   = (const float*)d_in[2];
    const float* Wq = (const float*)d_in[3];
    const float* bq = (const float*)d_in[4];
    const float* Wk = (const float*)d_in[5];
    const float* bk = (const float*)d_in[6];
    const float* Wv = (const float*)d_in[7];
    const float* bv = (const float*)d_in[8];
    const float* Wo = (const float*)d_in[9];
    const float* bo = (const float*)d_in[10];
    float* out = (float*)d_out;

    cudaFuncSetAttribute(attn_kernel, cudaFuncAttributeMaxDynamicSharedMemorySize, ATTN_SMEM);
    cudaFuncSetAttribute(qkv_gemm_kernel, cudaFuncAttributeMaxDynamicSharedMemorySize, GEMM_SMEM);
    cudaFuncSetAttribute(out_gemm_kernel, cudaFuncAttributeMaxDynamicSharedMemorySize, GEMM_SMEM);

    prep_w_kernel<<<dim3(D_ / 32, D_ / 32, 4), dim3(32, 8)>>>(Wq, Wk, Wv, Wo);
    qkv_gemm_kernel<<<dim3(D_ / 128, M_ / 128, 3), 256, GEMM_SMEM>>>(
        query, key, value, bq, bk, bv);
    attn_kernel<<<dim3(S_ / QROWS, B_ * H_), 128, ATTN_SMEM>>>();
    out_gemm_kernel<<<dim3(D_ / 128, M_ / 128), 256, GEMM_SMEM>>>(bo, out);
}